// round 2
// baseline (speedup 1.0000x reference)
#include <cuda_runtime.h>
#include <cstdint>
#include <cstddef>

#define NN   25000
#define EE   50000
#define EE3  40000
#define DIM  64

// ---------------- scratch (device globals; no allocation at launch time) ----
__device__ float g_h[NN * DIM];                     // node features / GRU state
__device__ float g_agg[NN * DIM];                   // scatter-sum accumulator
__device__ float g_hr[EE * 128];                    // edge hidden (relu(ea@W_e1))
__device__ float g_Wedge[(size_t)EE * DIM * DIM];   // 819 MB per-edge weight mats
__device__ float g_cnt[NN];
__device__ float g_invcnt[NN];

// ---------------- f32x2 helpers ---------------------------------------------
__device__ __forceinline__ unsigned long long fma2(unsigned long long a,
                                                   unsigned long long b,
                                                   unsigned long long c) {
    unsigned long long d;
    asm("fma.rn.f32x2 %0, %1, %2, %3;" : "=l"(d) : "l"(a), "l"(b), "l"(c));
    return d;
}
__device__ __forceinline__ float2 unpack2(unsigned long long v) {
    float2 r;
    asm("mov.b64 {%0, %1}, %2;" : "=f"(r.x), "=f"(r.y) : "l"(v));
    return r;
}

// ---------------- small kernels ----------------------------------------------
__global__ void zero_agg_kernel(int n) {
    int i = blockIdx.x * 256 + threadIdx.x;
    if (i < n) g_agg[i] = 0.f;
}
__global__ void zero_cnt_kernel(int n) {
    int i = blockIdx.x * 256 + threadIdx.x;
    if (i < n) g_cnt[i] = 0.f;
}
__global__ void count_kernel(const int* __restrict__ dst, int E) {
    int e = blockIdx.x * 256 + threadIdx.x;
    if (e < E) atomicAdd(&g_cnt[dst[e]], 1.f);
}
__global__ void invcnt_kernel(int N) {
    int i = blockIdx.x * 256 + threadIdx.x;
    if (i < N) g_invcnt[i] = 1.f / fmaxf(g_cnt[i], 1.f);
}

// out = relu(x @ W_node + b_node)   [N,8]x[8,64]
__global__ void node_mlp_kernel(const float* __restrict__ x,
                                const float* __restrict__ Wn,
                                const float* __restrict__ bn, int N) {
    int i = blockIdx.x * 256 + threadIdx.x;
    if (i >= N * DIM) return;
    int n = i >> 6, f = i & 63;
    float acc = bn[f];
#pragma unroll
    for (int k = 0; k < 8; k++) acc += x[n * 8 + k] * Wn[k * DIM + f];
    g_h[i] = fmaxf(acc, 0.f);
}

// per-edge: ea = relu(edge_attr@W_ea+b_ea) [19->12]; hr = relu(ea@W_e1+b_e1) [12->128]
__global__ void __launch_bounds__(128) edge_mlp_kernel(
    const float* __restrict__ ea_in, const float* __restrict__ W_ea,
    const float* __restrict__ b_ea, const float* __restrict__ W_e1,
    const float* __restrict__ b_e1, int E) {
    __shared__ float row[19];
    __shared__ float eah[12];
    int e = blockIdx.x;
    int tid = threadIdx.x;
    if (tid < 19) row[tid] = ea_in[(size_t)e * 19 + tid];
    __syncthreads();
    if (tid < 12) {
        float a = b_ea[tid];
#pragma unroll
        for (int i = 0; i < 19; i++) a += row[i] * W_ea[i * 12 + tid];
        eah[tid] = fmaxf(a, 0.f);
    }
    __syncthreads();
    float a = b_e1[tid];
#pragma unroll
    for (int k = 0; k < 12; k++) a += eah[k] * W_e1[k * 128 + tid];
    g_hr[(size_t)e * 128 + tid] = fmaxf(a, 0.f);
}

// Wedge[E,4096] = hr[E,128] @ W_e2[128,4096] + b_e2
// v2: 64 edges x 128 cols per 256-thread block. A-tile stored DUPLICATED in
// shared memory so ld.shared.b64 directly yields an f32x2 broadcast pair
// (no MOV-duplication in the inner loop). Per thread: 4 edges x 8 cols.
// Inner loop per k: 2 LDG.128 (B) + 4 LDS.64 (A, warp-broadcast) + 16 fma2.
__global__ void __launch_bounds__(256) wedge_gemm_kernel(
    const float* __restrict__ W2, const float* __restrict__ b2, int E) {
    extern __shared__ float a2[];   // [128][128]: a2[k][2e],a2[k][2e+1] = hr[e][k]
    int ebase = blockIdx.x * 64;
    int colbase = blockIdx.y * 128;
    int tid = threadIdx.x;

    // fill (el-major lanes: STS.64 conflict-free, LDS broadcast later)
#pragma unroll
    for (int batch = 0; batch < 8; batch++) {
        int i = batch * 256 + tid;          // i in [0, 2048)
        int el = i & 63;                    // edge slot
        int kq = i >> 6;                    // float4 index along k (0..31)
        int e = ebase + el;
        float4 v = make_float4(0.f, 0.f, 0.f, 0.f);
        if (e < E) v = *(const float4*)&g_hr[(size_t)e * 128 + kq * 4];
        float2* dst0 = (float2*)&a2[(kq * 4 + 0) * 128 + 2 * el];
        float2* dst1 = (float2*)&a2[(kq * 4 + 1) * 128 + 2 * el];
        float2* dst2 = (float2*)&a2[(kq * 4 + 2) * 128 + 2 * el];
        float2* dst3 = (float2*)&a2[(kq * 4 + 3) * 128 + 2 * el];
        *dst0 = make_float2(v.x, v.x);
        *dst1 = make_float2(v.y, v.y);
        *dst2 = make_float2(v.z, v.z);
        *dst3 = make_float2(v.w, v.w);
    }
    __syncthreads();

    int tx = tid & 15;   // 16 col groups of 8 cols
    int ty = tid >> 4;   // 16 edge groups of 4 edges
    unsigned long long acc[4][4];
#pragma unroll
    for (int i = 0; i < 4; i++)
#pragma unroll
        for (int j = 0; j < 4; j++) acc[i][j] = 0ull;

    const float* Wp = W2 + (size_t)colbase + tx * 8;
#pragma unroll 4
    for (int k = 0; k < 128; k++) {
        ulonglong2 bv0 = *reinterpret_cast<const ulonglong2*>(Wp + (size_t)k * 4096);
        ulonglong2 bv1 = *reinterpret_cast<const ulonglong2*>(Wp + (size_t)k * 4096 + 4);
#pragma unroll
        for (int e = 0; e < 4; e++) {
            unsigned long long ad =
                *(const unsigned long long*)&a2[k * 128 + 2 * (ty * 4 + e)];
            acc[e][0] = fma2(ad, bv0.x, acc[e][0]);
            acc[e][1] = fma2(ad, bv0.y, acc[e][1]);
            acc[e][2] = fma2(ad, bv1.x, acc[e][2]);
            acc[e][3] = fma2(ad, bv1.y, acc[e][3]);
        }
    }

    float4 bias0 = *(const float4*)&b2[colbase + tx * 8];
    float4 bias1 = *(const float4*)&b2[colbase + tx * 8 + 4];
#pragma unroll
    for (int e = 0; e < 4; e++) {
        int edge = ebase + ty * 4 + e;
        if (edge < E) {
            float2 p0 = unpack2(acc[e][0]);
            float2 p1 = unpack2(acc[e][1]);
            float2 p2 = unpack2(acc[e][2]);
            float2 p3 = unpack2(acc[e][3]);
            float* op = g_Wedge + (size_t)edge * 4096 + colbase + tx * 8;
            *(float4*)op = make_float4(p0.x + bias0.x, p0.y + bias0.y,
                                       p1.x + bias0.z, p1.y + bias0.w);
            *(float4*)(op + 4) = make_float4(p2.x + bias1.x, p2.y + bias1.y,
                                             p3.x + bias1.z, p3.y + bias1.w);
        }
    }
}

// msg[e] = h[src[e]] @ Wedge[e]; atomically scattered to g_agg[dst[e]].
// 16 edges per 256-thread block; 16 threads per edge, 4 cols each (float4 reads).
__global__ void __launch_bounds__(256) msg_scatter_kernel(
    const int* __restrict__ src, const int* __restrict__ dst, int E) {
    __shared__ float outs[16][64];
    int ty = threadIdx.x >> 4;   // edge slot
    int tx = threadIdx.x & 15;   // col group
    int e = blockIdx.x * 16 + ty;
    if (e < E) {
        int s = src[e];
        *(float4*)&outs[ty][tx * 4] = *(const float4*)&g_h[(size_t)s * 64 + tx * 4];
    }
    __syncthreads();
    if (e >= E) return;
    float a0 = 0.f, a1 = 0.f, a2 = 0.f, a3 = 0.f;
    const float4* Wp = (const float4*)(g_Wedge + (size_t)e * 4096) + tx;
#pragma unroll 8
    for (int d = 0; d < 64; d++) {
        float a = outs[ty][d];
        float4 w = Wp[d * 16];
        a0 += a * w.x; a1 += a * w.y; a2 += a * w.z; a3 += a * w.w;
    }
    int dn = dst[e];
    float* ap = g_agg + (size_t)dn * 64 + tx * 4;
    atomicAdd(ap + 0, a0);
    atomicAdd(ap + 1, a1);
    atomicAdd(ap + 2, a2);
    atomicAdd(ap + 3, a3);
}

// GRU update, 32 nodes per block; W_ih/W_hh staged in padded dynamic shared.
// v2: register-blocked — each thread owns (feature lane, 8 nodes); per k:
// 6 weight LDS + 16 broadcast LDS feed 48 FMAs.
#define GRU_NODES 32
#define GRU_SMEM_FLOATS (2 * 192 * 65 + 2 * GRU_NODES * 64)
__global__ void __launch_bounds__(256) gru_kernel(
    const float* __restrict__ conv_bias,
    const float* __restrict__ W_ih, const float* __restrict__ b_ih,
    const float* __restrict__ W_hh, const float* __restrict__ b_hh, int N) {
    extern __shared__ float sm[];
    float* wih = sm;                     // [192][65] padded
    float* whh = sm + 192 * 65;
    float* ms  = whh + 192 * 65;         // [32][64]
    float* hs  = ms + GRU_NODES * 64;    // [32][64]
    int tid = threadIdx.x;
    for (int i = tid; i < 192 * 64; i += 256) {
        int j = i >> 6, k = i & 63;
        wih[j * 65 + k] = W_ih[i];
        whh[j * 65 + k] = W_hh[i];
    }
    int nb = blockIdx.x * GRU_NODES;
    for (int i = tid; i < GRU_NODES * 64; i += 256) {
        int nl = i >> 6, f = i & 63;
        int n = nb + nl;
        if (n < N) {
            ms[nl * 64 + f] =
                fmaxf(g_agg[(size_t)n * 64 + f] * g_invcnt[n] + conv_bias[f], 0.f);
            hs[nl * 64 + f] = g_h[(size_t)n * 64 + f];
        }
    }
    __syncthreads();
    int lane = tid & 63;   // feature f
    int grp = tid >> 6;    // 0..3 -> nodes grp*8 .. grp*8+7
    float aR[8], aZ[8], aN[8], bR[8], bZ[8], bN[8];
    {
        float bir = b_ih[lane], biz = b_ih[64 + lane], bin = b_ih[128 + lane];
        float bhr = b_hh[lane], bhz = b_hh[64 + lane], bhn = b_hh[128 + lane];
#pragma unroll
        for (int j = 0; j < 8; j++) {
            aR[j] = bir; aZ[j] = biz; aN[j] = bin;
            bR[j] = bhr; bZ[j] = bhz; bN[j] = bhn;
        }
    }
    const float* msg = ms + grp * 8 * 64;
    const float* hsg = hs + grp * 8 * 64;
#pragma unroll 2
    for (int k = 0; k < 64; k++) {
        float w0 = wih[lane * 65 + k];
        float w1 = wih[(64 + lane) * 65 + k];
        float w2 = wih[(128 + lane) * 65 + k];
        float v0 = whh[lane * 65 + k];
        float v1 = whh[(64 + lane) * 65 + k];
        float v2 = whh[(128 + lane) * 65 + k];
#pragma unroll
        for (int j = 0; j < 8; j++) {
            float mk = msg[j * 64 + k];
            float hk = hsg[j * 64 + k];
            aR[j] += mk * w0; aZ[j] += mk * w1; aN[j] += mk * w2;
            bR[j] += hk * v0; bZ[j] += hk * v1; bN[j] += hk * v2;
        }
    }
#pragma unroll
    for (int j = 0; j < 8; j++) {
        int n = nb + grp * 8 + j;
        if (n >= N) continue;
        float r = 1.f / (1.f + __expf(-(aR[j] + bR[j])));
        float z = 1.f / (1.f + __expf(-(aZ[j] + bZ[j])));
        float ng = tanhf(aN[j] + r * bN[j]);
        g_h[(size_t)n * 64 + lane] =
            (1.f - z) * ng + z * hsg[j * 64 + lane];
    }
}

// final: feat=[0.5*(h[a]+h[b]) (64) | edge_attr3 (8)]; y = relu(feat@W_l1+b_l1)@W_l2+b_l2
#define FIN_PER_BLOCK 32
__global__ void __launch_bounds__(128) final_mlp_kernel(
    const float* __restrict__ ea3, const int* __restrict__ idx_a,
    const int* __restrict__ idx_b, const float* __restrict__ W_l1,
    const float* __restrict__ b_l1, const float* __restrict__ W_l2,
    const float* __restrict__ b_l2, float* __restrict__ out, int E3) {
    __shared__ float wl1[72 * 128];
    __shared__ float wl2[128];
    __shared__ float feat[72];
    __shared__ float red[4];
    int tid = threadIdx.x;
    for (int i = tid; i < 72 * 128; i += 128) wl1[i] = W_l1[i];
    wl2[tid] = W_l2[tid];
    float bl1 = b_l1[tid];
    int base = blockIdx.x * FIN_PER_BLOCK;
    for (int t = 0; t < FIN_PER_BLOCK; t++) {
        int e = base + t;
        if (e >= E3) break;
        __syncthreads();   // protects feat/red reuse + first-iter staging
        if (tid < 64) {
            int a = idx_a[e], b = idx_b[e];
            feat[tid] = 0.5f * (g_h[(size_t)a * 64 + tid] + g_h[(size_t)b * 64 + tid]);
        } else if (tid < 72) {
            feat[tid] = ea3[(size_t)e * 8 + (tid - 64)];
        }
        __syncthreads();
        float acc = bl1;
#pragma unroll
        for (int i = 0; i < 72; i++) acc += feat[i] * wl1[i * 128 + tid];
        acc = fmaxf(acc, 0.f) * wl2[tid];
#pragma unroll
        for (int o = 16; o > 0; o >>= 1) acc += __shfl_down_sync(0xffffffffu, acc, o);
        if ((tid & 31) == 0) red[tid >> 5] = acc;
        __syncthreads();
        if (tid == 0) out[e] = red[0] + red[1] + red[2] + red[3] + b_l2[0];
    }
}

// ---------------- launch ------------------------------------------------------
extern "C" void kernel_launch(void* const* d_in, const int* in_sizes, int n_in,
                              void* d_out, int out_size) {
    const float* x          = (const float*)d_in[0];
    const float* edge_attr  = (const float*)d_in[1];
    const float* edge_attr3 = (const float*)d_in[2];
    const int*   edge_index  = (const int*)d_in[3];
    const int*   edge_index3 = (const int*)d_in[4];
    const float* W_node = (const float*)d_in[5];
    const float* b_node = (const float*)d_in[6];
    const float* W_ea   = (const float*)d_in[7];
    const float* b_ea   = (const float*)d_in[8];
    const float* W_e1   = (const float*)d_in[9];
    const float* b_e1   = (const float*)d_in[10];
    const float* W_e2   = (const float*)d_in[11];
    const float* b_e2   = (const float*)d_in[12];
    const float* conv_bias = (const float*)d_in[13];
    const float* W_ih = (const float*)d_in[14];
    const float* b_ih = (const float*)d_in[15];
    const float* W_hh = (const float*)d_in[16];
    const float* b_hh = (const float*)d_in[17];
    const float* W_l1 = (const float*)d_in[18];
    const float* b_l1 = (const float*)d_in[19];
    const float* W_l2 = (const float*)d_in[20];
    const float* b_l2 = (const float*)d_in[21];

    int N  = in_sizes[0] / 8;
    int E  = in_sizes[1] / 19;
    int E3 = in_sizes[2] / 8;
    const int* src  = edge_index;
    const int* dst  = edge_index + E;
    const int* e3a  = edge_index3;
    const int* e3b  = edge_index3 + E3;
    float* out = (float*)d_out;

    cudaFuncSetAttribute(gru_kernel, cudaFuncAttributeMaxDynamicSharedMemorySize,
                         GRU_SMEM_FLOATS * (int)sizeof(float));
    cudaFuncSetAttribute(wedge_gemm_kernel,
                         cudaFuncAttributeMaxDynamicSharedMemorySize,
                         128 * 128 * (int)sizeof(float));

    // 1. node MLP
    node_mlp_kernel<<<(N * DIM + 255) / 256, 256>>>(x, W_node, b_node, N);
    // 2. edge MLP -> hr
    edge_mlp_kernel<<<E, 128>>>(edge_attr, W_ea, b_ea, W_e1, b_e1, E);
    // 3. big GEMM -> Wedge
    {
        dim3 grid((E + 63) / 64, 32);
        wedge_gemm_kernel<<<grid, 256, 128 * 128 * sizeof(float)>>>(W_e2, b_e2, E);
    }
    // 4. degree counts
    zero_cnt_kernel<<<(N + 255) / 256, 256>>>(N);
    count_kernel<<<(E + 255) / 256, 256>>>(dst, E);
    invcnt_kernel<<<(N + 255) / 256, 256>>>(N);
    // 5. three conv + GRU iterations
    for (int it = 0; it < 3; it++) {
        zero_agg_kernel<<<(N * DIM + 255) / 256, 256>>>(N * DIM);
        msg_scatter_kernel<<<(E + 15) / 16, 256>>>(src, dst, E);
        gru_kernel<<<(N + GRU_NODES - 1) / GRU_NODES, 256,
                     GRU_SMEM_FLOATS * (int)sizeof(float)>>>(
            conv_bias, W_ih, b_ih, W_hh, b_hh, N);
    }
    // 6. final pair MLP
    final_mlp_kernel<<<(E3 + FIN_PER_BLOCK - 1) / FIN_PER_BLOCK, 128>>>(
        edge_attr3, e3a, e3b, W_l1, b_l1, W_l2, b_l2, out, E3);
}

// round 3
// speedup vs baseline: 1.2419x; 1.2419x over previous
#include <cuda_runtime.h>
#include <cuda_fp16.h>
#include <cstdint>
#include <cstddef>

#define NN   25000
#define EE   50000
#define EE3  40000
#define DIM  64

// ---------------- scratch (device globals; no allocation at launch time) ----
__device__ float g_h[NN * DIM];                       // node features / GRU state
__device__ float g_agg[NN * DIM];                     // scatter-sum accumulator
__device__ float g_hr[EE * 128];                      // edge hidden
__device__ __half g_Wedge_h[(size_t)EE * DIM * DIM];  // 410 MB per-edge weights (fp16)
__device__ float g_cnt[NN];
__device__ float g_invcnt[NN];

// ---------------- f32x2 helpers ---------------------------------------------
__device__ __forceinline__ unsigned long long fma2(unsigned long long a,
                                                   unsigned long long b,
                                                   unsigned long long c) {
    unsigned long long d;
    asm("fma.rn.f32x2 %0, %1, %2, %3;" : "=l"(d) : "l"(a), "l"(b), "l"(c));
    return d;
}
__device__ __forceinline__ unsigned long long dup2(float x) {
    unsigned long long d;
    asm("mov.b64 %0, {%1, %1};" : "=l"(d) : "f"(x));
    return d;
}
__device__ __forceinline__ float2 unpack2(unsigned long long v) {
    float2 r;
    asm("mov.b64 {%0, %1}, %2;" : "=f"(r.x), "=f"(r.y) : "l"(v));
    return r;
}

// ---------------- small kernels ----------------------------------------------
__global__ void zero_agg_kernel(int n) {
    int i = blockIdx.x * 256 + threadIdx.x;
    if (i < n) g_agg[i] = 0.f;
}
__global__ void zero_cnt_kernel(int n) {
    int i = blockIdx.x * 256 + threadIdx.x;
    if (i < n) g_cnt[i] = 0.f;
}
__global__ void count_kernel(const int* __restrict__ dst, int E) {
    int e = blockIdx.x * 256 + threadIdx.x;
    if (e < E) atomicAdd(&g_cnt[dst[e]], 1.f);
}
__global__ void invcnt_kernel(int N) {
    int i = blockIdx.x * 256 + threadIdx.x;
    if (i < N) g_invcnt[i] = 1.f / fmaxf(g_cnt[i], 1.f);
}

// out = relu(x @ W_node + b_node)   [N,8]x[8,64]
__global__ void node_mlp_kernel(const float* __restrict__ x,
                                const float* __restrict__ Wn,
                                const float* __restrict__ bn, int N) {
    int i = blockIdx.x * 256 + threadIdx.x;
    if (i >= N * DIM) return;
    int n = i >> 6, f = i & 63;
    float acc = bn[f];
#pragma unroll
    for (int k = 0; k < 8; k++) acc += x[n * 8 + k] * Wn[k * DIM + f];
    g_h[i] = fmaxf(acc, 0.f);
}

// per-edge: ea = relu(edge_attr@W_ea+b_ea) [19->12]; hr = relu(ea@W_e1+b_e1) [12->128]
__global__ void __launch_bounds__(128) edge_mlp_kernel(
    const float* __restrict__ ea_in, const float* __restrict__ W_ea,
    const float* __restrict__ b_ea, const float* __restrict__ W_e1,
    const float* __restrict__ b_e1, int E) {
    __shared__ float row[19];
    __shared__ float eah[12];
    int e = blockIdx.x;
    int tid = threadIdx.x;
    if (tid < 19) row[tid] = ea_in[(size_t)e * 19 + tid];
    __syncthreads();
    if (tid < 12) {
        float a = b_ea[tid];
#pragma unroll
        for (int i = 0; i < 19; i++) a += row[i] * W_ea[i * 12 + tid];
        eah[tid] = fmaxf(a, 0.f);
    }
    __syncthreads();
    float a = b_e1[tid];
#pragma unroll
    for (int k = 0; k < 12; k++) a += eah[k] * W_e1[k * 128 + tid];
    g_hr[(size_t)e * 128 + tid] = fmaxf(a, 0.f);
}

// Wedge[E,4096] = hr[E,128] @ W_e2[128,4096] + b_e2, stored fp16.
// v3: 128 edges x 64 cols per 256-thread block. BOTH tiles in smem (96 KB):
// no global loads in the inner loop (v2 was L2-bound on W2 re-reads).
// Per thread: 4 edges x 8 cols. Inner loop per k:
//   4 LDS.32 (A broadcast) + dup MOVs (alu pipe) + 2 LDS.128 (B) + 16 fma2.
#define GE_TE 128
#define GE_TC 64
#define GE_SMEM_FLOATS (GE_TE * 128 + 128 * GE_TC)
__global__ void __launch_bounds__(256) wedge_gemm_kernel(
    const float* __restrict__ W2, const float* __restrict__ b2, int E) {
    extern __shared__ float sm[];
    float* As = sm;                 // [128 edges][128 k]
    float* Bs = sm + GE_TE * 128;   // [128 k][64 cols]
    int ebase = blockIdx.x * GE_TE;
    int colbase = blockIdx.y * GE_TC;
    int tid = threadIdx.x;

    // fill A (coalesced LDG.128, conflict-free STS.128)
#pragma unroll
    for (int it = 0; it < 16; it++) {
        int i = it * 256 + tid;
        int kq = i & 31, el = i >> 5;
        int e = ebase + el;
        float4 v = make_float4(0.f, 0.f, 0.f, 0.f);
        if (e < E) v = *(const float4*)&g_hr[(size_t)e * 128 + kq * 4];
        *(float4*)&As[el * 128 + kq * 4] = v;
    }
    // fill B
#pragma unroll
    for (int it = 0; it < 8; it++) {
        int i = it * 256 + tid;
        int c4 = i & 15, k = i >> 4;
        *(float4*)&Bs[k * 64 + c4 * 4] =
            *(const float4*)&W2[(size_t)k * 4096 + colbase + c4 * 4];
    }
    __syncthreads();

    int tx = tid & 7;    // 8 col groups of 8 cols
    int ty = tid >> 3;   // 32 edge groups of 4 edges
    unsigned long long acc[4][4];
#pragma unroll
    for (int i = 0; i < 4; i++)
#pragma unroll
        for (int j = 0; j < 4; j++) acc[i][j] = 0ull;

    const float* Ap = As + ty * 4 * 128;
    const float* Bp = Bs + tx * 8;
#pragma unroll 4
    for (int k = 0; k < 128; k++) {
        ulonglong2 b0 = *(const ulonglong2*)&Bp[k * 64];
        ulonglong2 b1 = *(const ulonglong2*)&Bp[k * 64 + 4];
#pragma unroll
        for (int e = 0; e < 4; e++) {
            unsigned long long ad = dup2(Ap[e * 128 + k]);
            acc[e][0] = fma2(ad, b0.x, acc[e][0]);
            acc[e][1] = fma2(ad, b0.y, acc[e][1]);
            acc[e][2] = fma2(ad, b1.x, acc[e][2]);
            acc[e][3] = fma2(ad, b1.y, acc[e][3]);
        }
    }

    float4 bias0 = *(const float4*)&b2[colbase + tx * 8];
    float4 bias1 = *(const float4*)&b2[colbase + tx * 8 + 4];
#pragma unroll
    for (int e = 0; e < 4; e++) {
        int edge = ebase + ty * 4 + e;
        if (edge < E) {
            float2 p0 = unpack2(acc[e][0]);
            float2 p1 = unpack2(acc[e][1]);
            float2 p2 = unpack2(acc[e][2]);
            float2 p3 = unpack2(acc[e][3]);
            __half2 h0 = __floats2half2_rn(p0.x + bias0.x, p0.y + bias0.y);
            __half2 h1 = __floats2half2_rn(p1.x + bias0.z, p1.y + bias0.w);
            __half2 h2 = __floats2half2_rn(p2.x + bias1.x, p2.y + bias1.y);
            __half2 h3 = __floats2half2_rn(p3.x + bias1.z, p3.y + bias1.w);
            uint4 st;
            st.x = *(unsigned int*)&h0;
            st.y = *(unsigned int*)&h1;
            st.z = *(unsigned int*)&h2;
            st.w = *(unsigned int*)&h3;
            *(uint4*)(g_Wedge_h + (size_t)edge * 4096 + colbase + tx * 8) = st;
        }
    }
}

// msg[e] = h[src[e]] @ Wedge_h[e] (fp16 weights, fp32 accumulate);
// atomically scattered to g_agg[dst[e]]. 32 edges/block, 8 threads/edge x 8 cols.
__global__ void __launch_bounds__(256) msg_scatter_kernel(
    const int* __restrict__ src, const int* __restrict__ dst, int E) {
    __shared__ float outs[32][68];   // padded: stride 68 -> conflict-free col reads
    __shared__ int sdst[32];
    int ty = threadIdx.x >> 3;   // edge slot
    int tx = threadIdx.x & 7;    // col group (8 cols)
    int e = blockIdx.x * 32 + ty;
    if (e < E) {
        int s = src[e];
        *(float4*)&outs[ty][tx * 8] =
            *(const float4*)&g_h[(size_t)s * 64 + tx * 8];
        *(float4*)&outs[ty][tx * 8 + 4] =
            *(const float4*)&g_h[(size_t)s * 64 + tx * 8 + 4];
        if (tx == 0) sdst[ty] = dst[e];
    }
    __syncthreads();
    if (e >= E) return;
    float acc[8];
#pragma unroll
    for (int j = 0; j < 8; j++) acc[j] = 0.f;
    const __half* Wrow = g_Wedge_h + (size_t)e * 4096 + tx * 8;
#pragma unroll 4
    for (int d = 0; d < 64; d++) {
        float a = outs[ty][d];
        uint4 raw = *(const uint4*)(Wrow + d * 64);
        float2 f0 = __half22float2(*(__half2*)&raw.x);
        float2 f1 = __half22float2(*(__half2*)&raw.y);
        float2 f2 = __half22float2(*(__half2*)&raw.z);
        float2 f3 = __half22float2(*(__half2*)&raw.w);
        acc[0] += a * f0.x; acc[1] += a * f0.y;
        acc[2] += a * f1.x; acc[3] += a * f1.y;
        acc[4] += a * f2.x; acc[5] += a * f2.y;
        acc[6] += a * f3.x; acc[7] += a * f3.y;
    }
    int dn = sdst[ty];
    float* ap = g_agg + (size_t)dn * 64 + tx * 8;
#pragma unroll
    for (int j = 0; j < 8; j++) atomicAdd(ap + j, acc[j]);
}

// GRU update, 32 nodes per block; register-blocked 8 nodes/thread.
#define GRU_NODES 32
#define GRU_SMEM_FLOATS (2 * 192 * 65 + 2 * GRU_NODES * 64)
__global__ void __launch_bounds__(256) gru_kernel(
    const float* __restrict__ conv_bias,
    const float* __restrict__ W_ih, const float* __restrict__ b_ih,
    const float* __restrict__ W_hh, const float* __restrict__ b_hh, int N) {
    extern __shared__ float sm[];
    float* wih = sm;                     // [192][65] padded
    float* whh = sm + 192 * 65;
    float* ms  = whh + 192 * 65;         // [32][64]
    float* hs  = ms + GRU_NODES * 64;    // [32][64]
    int tid = threadIdx.x;
    for (int i = tid; i < 192 * 64; i += 256) {
        int j = i >> 6, k = i & 63;
        wih[j * 65 + k] = W_ih[i];
        whh[j * 65 + k] = W_hh[i];
    }
    int nb = blockIdx.x * GRU_NODES;
    for (int i = tid; i < GRU_NODES * 64; i += 256) {
        int nl = i >> 6, f = i & 63;
        int n = nb + nl;
        if (n < N) {
            ms[nl * 64 + f] =
                fmaxf(g_agg[(size_t)n * 64 + f] * g_invcnt[n] + conv_bias[f], 0.f);
            hs[nl * 64 + f] = g_h[(size_t)n * 64 + f];
        }
    }
    __syncthreads();
    int lane = tid & 63;
    int grp = tid >> 6;
    float aR[8], aZ[8], aN[8], bR[8], bZ[8], bN[8];
    {
        float bir = b_ih[lane], biz = b_ih[64 + lane], bin = b_ih[128 + lane];
        float bhr = b_hh[lane], bhz = b_hh[64 + lane], bhn = b_hh[128 + lane];
#pragma unroll
        for (int j = 0; j < 8; j++) {
            aR[j] = bir; aZ[j] = biz; aN[j] = bin;
            bR[j] = bhr; bZ[j] = bhz; bN[j] = bhn;
        }
    }
    const float* msg = ms + grp * 8 * 64;
    const float* hsg = hs + grp * 8 * 64;
#pragma unroll 2
    for (int k = 0; k < 64; k++) {
        float w0 = wih[lane * 65 + k];
        float w1 = wih[(64 + lane) * 65 + k];
        float w2 = wih[(128 + lane) * 65 + k];
        float v0 = whh[lane * 65 + k];
        float v1 = whh[(64 + lane) * 65 + k];
        float v2 = whh[(128 + lane) * 65 + k];
#pragma unroll
        for (int j = 0; j < 8; j++) {
            float mk = msg[j * 64 + k];
            float hk = hsg[j * 64 + k];
            aR[j] += mk * w0; aZ[j] += mk * w1; aN[j] += mk * w2;
            bR[j] += hk * v0; bZ[j] += hk * v1; bN[j] += hk * v2;
        }
    }
#pragma unroll
    for (int j = 0; j < 8; j++) {
        int n = nb + grp * 8 + j;
        if (n >= N) continue;
        float r = 1.f / (1.f + __expf(-(aR[j] + bR[j])));
        float z = 1.f / (1.f + __expf(-(aZ[j] + bZ[j])));
        float ng = tanhf(aN[j] + r * bN[j]);
        g_h[(size_t)n * 64 + lane] =
            (1.f - z) * ng + z * hsg[j * 64 + lane];
    }
}

// final: feat=[0.5*(h[a]+h[b]) (64) | edge_attr3 (8)]; y = relu(feat@W_l1+b_l1)@W_l2+b_l2
#define FIN_PER_BLOCK 32
__global__ void __launch_bounds__(128) final_mlp_kernel(
    const float* __restrict__ ea3, const int* __restrict__ idx_a,
    const int* __restrict__ idx_b, const float* __restrict__ W_l1,
    const float* __restrict__ b_l1, const float* __restrict__ W_l2,
    const float* __restrict__ b_l2, float* __restrict__ out, int E3) {
    __shared__ float wl1[72 * 128];
    __shared__ float wl2[128];
    __shared__ float feat[72];
    __shared__ float red[4];
    int tid = threadIdx.x;
    for (int i = tid; i < 72 * 128; i += 128) wl1[i] = W_l1[i];
    wl2[tid] = W_l2[tid];
    float bl1 = b_l1[tid];
    int base = blockIdx.x * FIN_PER_BLOCK;
    for (int t = 0; t < FIN_PER_BLOCK; t++) {
        int e = base + t;
        if (e >= E3) break;
        __syncthreads();
        if (tid < 64) {
            int a = idx_a[e], b = idx_b[e];
            feat[tid] = 0.5f * (g_h[(size_t)a * 64 + tid] + g_h[(size_t)b * 64 + tid]);
        } else if (tid < 72) {
            feat[tid] = ea3[(size_t)e * 8 + (tid - 64)];
        }
        __syncthreads();
        float acc = bl1;
#pragma unroll
        for (int i = 0; i < 72; i++) acc += feat[i] * wl1[i * 128 + tid];
        acc = fmaxf(acc, 0.f) * wl2[tid];
#pragma unroll
        for (int o = 16; o > 0; o >>= 1) acc += __shfl_down_sync(0xffffffffu, acc, o);
        if ((tid & 31) == 0) red[tid >> 5] = acc;
        __syncthreads();
        if (tid == 0) out[e] = red[0] + red[1] + red[2] + red[3] + b_l2[0];
    }
}

// ---------------- launch ------------------------------------------------------
extern "C" void kernel_launch(void* const* d_in, const int* in_sizes, int n_in,
                              void* d_out, int out_size) {
    const float* x          = (const float*)d_in[0];
    const float* edge_attr  = (const float*)d_in[1];
    const float* edge_attr3 = (const float*)d_in[2];
    const int*   edge_index  = (const int*)d_in[3];
    const int*   edge_index3 = (const int*)d_in[4];
    const float* W_node = (const float*)d_in[5];
    const float* b_node = (const float*)d_in[6];
    const float* W_ea   = (const float*)d_in[7];
    const float* b_ea   = (const float*)d_in[8];
    const float* W_e1   = (const float*)d_in[9];
    const float* b_e1   = (const float*)d_in[10];
    const float* W_e2   = (const float*)d_in[11];
    const float* b_e2   = (const float*)d_in[12];
    const float* conv_bias = (const float*)d_in[13];
    const float* W_ih = (const float*)d_in[14];
    const float* b_ih = (const float*)d_in[15];
    const float* W_hh = (const float*)d_in[16];
    const float* b_hh = (const float*)d_in[17];
    const float* W_l1 = (const float*)d_in[18];
    const float* b_l1 = (const float*)d_in[19];
    const float* W_l2 = (const float*)d_in[20];
    const float* b_l2 = (const float*)d_in[21];

    int N  = in_sizes[0] / 8;
    int E  = in_sizes[1] / 19;
    int E3 = in_sizes[2] / 8;
    const int* src  = edge_index;
    const int* dst  = edge_index + E;
    const int* e3a  = edge_index3;
    const int* e3b  = edge_index3 + E3;
    float* out = (float*)d_out;

    cudaFuncSetAttribute(gru_kernel, cudaFuncAttributeMaxDynamicSharedMemorySize,
                         GRU_SMEM_FLOATS * (int)sizeof(float));
    cudaFuncSetAttribute(wedge_gemm_kernel,
                         cudaFuncAttributeMaxDynamicSharedMemorySize,
                         GE_SMEM_FLOATS * (int)sizeof(float));

    // degree counts first (also positions the big GEMM at the ncu capture slot)
    zero_cnt_kernel<<<(N + 255) / 256, 256>>>(N);
    count_kernel<<<(E + 255) / 256, 256>>>(dst, E);
    invcnt_kernel<<<(N + 255) / 256, 256>>>(N);
    // node MLP
    node_mlp_kernel<<<(N * DIM + 255) / 256, 256>>>(x, W_node, b_node, N);
    // edge MLP -> hr
    edge_mlp_kernel<<<E, 128>>>(edge_attr, W_ea, b_ea, W_e1, b_e1, E);
    // big GEMM -> Wedge (fp16)
    {
        dim3 grid((E + GE_TE - 1) / GE_TE, 4096 / GE_TC);
        wedge_gemm_kernel<<<grid, 256, GE_SMEM_FLOATS * sizeof(float)>>>(
            W_e2, b_e2, E);
    }
    // three conv + GRU iterations
    for (int it = 0; it < 3; it++) {
        zero_agg_kernel<<<(N * DIM + 255) / 256, 256>>>(N * DIM);
        msg_scatter_kernel<<<(E + 31) / 32, 256>>>(src, dst, E);
        gru_kernel<<<(N + GRU_NODES - 1) / GRU_NODES, 256,
                     GRU_SMEM_FLOATS * (int)sizeof(float)>>>(
            conv_bias, W_ih, b_ih, W_hh, b_hh, N);
    }
    // final pair MLP
    final_mlp_kernel<<<(E3 + FIN_PER_BLOCK - 1) / FIN_PER_BLOCK, 128>>>(
        edge_attr3, e3a, e3b, W_l1, b_l1, W_l2, b_l2, out, E3);
}

// round 5
// speedup vs baseline: 3.4568x; 2.7835x over previous
#include <cuda_runtime.h>
#include <cuda_fp16.h>
#include <cstdint>
#include <cstddef>

#define NN   25000
#define EE   50000
#define EE3  40000
#define DIM  64

// ---------------- scratch (device globals; no allocation at launch time) ----
__device__ float  g_h[NN * DIM];                       // node features / GRU state
__device__ float  g_agg[NN * DIM];                     // scatter-sum accumulator
__device__ __half g_hr_h[EE * 128];                    // edge hidden (fp16)
__device__ __half g_W2T[4096 * 128];                   // W_e2 transposed fp16 [col][k]
__device__ __half g_Wedge_h[(size_t)EE * DIM * DIM];   // 410 MB per-edge weights
__device__ float  g_cnt[NN];
__device__ float  g_invcnt[NN];

// ---------------- warp MMA helpers (sm_80+ PTX: safe for compute_103) --------
__device__ __forceinline__ uint32_t smem_to_u32(const void* p) {
    uint32_t a;
    asm("{ .reg .u64 t; cvta.to.shared.u64 t, %1; cvt.u32.u64 %0, t; }"
        : "=r"(a) : "l"(p));
    return a;
}
__device__ __forceinline__ void ldsm4(uint32_t* r, uint32_t addr) {
    asm volatile("ldmatrix.sync.aligned.m8n8.x4.shared.b16 {%0,%1,%2,%3}, [%4];"
                 : "=r"(r[0]), "=r"(r[1]), "=r"(r[2]), "=r"(r[3]) : "r"(addr));
}
__device__ __forceinline__ void mma16816(float* d, const uint32_t* a,
                                         const uint32_t* b) {
    asm volatile(
        "mma.sync.aligned.m16n8k16.row.col.f32.f16.f16.f32 "
        "{%0,%1,%2,%3}, {%4,%5,%6,%7}, {%8,%9}, {%0,%1,%2,%3};"
        : "+f"(d[0]), "+f"(d[1]), "+f"(d[2]), "+f"(d[3])
        : "r"(a[0]), "r"(a[1]), "r"(a[2]), "r"(a[3]), "r"(b[0]), "r"(b[1]));
}

// ---------------- small kernels ----------------------------------------------
__global__ void zero_agg_kernel(int n) {
    int i = blockIdx.x * 256 + threadIdx.x;
    if (i < n) g_agg[i] = 0.f;
}
__global__ void zero_cnt_kernel(int n) {
    int i = blockIdx.x * 256 + threadIdx.x;
    if (i < n) g_cnt[i] = 0.f;
}
__global__ void count_kernel(const int* __restrict__ dst, int E) {
    int e = blockIdx.x * 256 + threadIdx.x;
    if (e < E) atomicAdd(&g_cnt[dst[e]], 1.f);
}
__global__ void invcnt_kernel(int N) {
    int i = blockIdx.x * 256 + threadIdx.x;
    if (i < N) g_invcnt[i] = 1.f / fmaxf(g_cnt[i], 1.f);
}

// out = relu(x @ W_node + b_node)   [N,8]x[8,64]
__global__ void node_mlp_kernel(const float* __restrict__ x,
                                const float* __restrict__ Wn,
                                const float* __restrict__ bn, int N) {
    int i = blockIdx.x * 256 + threadIdx.x;
    if (i >= N * DIM) return;
    int n = i >> 6, f = i & 63;
    float acc = bn[f];
#pragma unroll
    for (int k = 0; k < 8; k++) acc += x[n * 8 + k] * Wn[k * DIM + f];
    g_h[i] = fmaxf(acc, 0.f);
}

// W_e2 [128,4096] fp32 -> g_W2T [4096][128] fp16
__global__ void w2_transpose_kernel(const float* __restrict__ W2) {
    int i = blockIdx.x * 256 + threadIdx.x;
    if (i >= 4096 * 128) return;
    int n = i & 4095, k = i >> 12;
    g_W2T[(size_t)n * 128 + k] = __float2half(W2[(size_t)k * 4096 + n]);
}

// per-edge: ea = relu(edge_attr@W_ea+b_ea) [19->12]; hr = relu(ea@W_e1+b_e1) [12->128] fp16
__global__ void __launch_bounds__(128) edge_mlp_kernel(
    const float* __restrict__ ea_in, const float* __restrict__ W_ea,
    const float* __restrict__ b_ea, const float* __restrict__ W_e1,
    const float* __restrict__ b_e1, int E) {
    __shared__ float row[19];
    __shared__ float eah[12];
    int e = blockIdx.x;
    int tid = threadIdx.x;
    if (tid < 19) row[tid] = ea_in[(size_t)e * 19 + tid];
    __syncthreads();
    if (tid < 12) {
        float a = b_ea[tid];
#pragma unroll
        for (int i = 0; i < 19; i++) a += row[i] * W_ea[i * 12 + tid];
        eah[tid] = fmaxf(a, 0.f);
    }
    __syncthreads();
    float a = b_e1[tid];
#pragma unroll
    for (int k = 0; k < 12; k++) a += eah[k] * W_e1[k * 128 + tid];
    g_hr_h[(size_t)e * 128 + tid] = __float2half(fmaxf(a, 0.f));
}

// ============ HMMA Wedge GEMM =================================================
// Wedge[E,4096] = hr[E,128] @ W_e2[128,4096] + b_e2, on tensor cores via
// mma.sync.m16n8k16 (fp16 in, fp32 acc). Per CTA: 128x128x128 tile.
// A = hr rows (M), B = W2T rows (N, "col" layout: [n][k]).
// smem tiles padded to 136 halves/row -> conflict-free ldmatrix.
#define WSTRIDE 136
#define AS_OFF  0
#define BS_OFF  (128 * WSTRIDE * 2)
#define BIAS_OFF (2 * 128 * WSTRIDE * 2)
#define WM_SMEM_SIZE (BIAS_OFF + 128 * 4)

__global__ void __launch_bounds__(256) wedge_mma_kernel(
    const float* __restrict__ b2, int E) {
    extern __shared__ char smem[];
    __half* As = (__half*)(smem + AS_OFF);
    __half* Bs = (__half*)(smem + BS_OFF);
    float* sbias = (float*)(smem + BIAS_OFF);
    uint32_t sbase = smem_to_u32(smem);
    int tid = threadIdx.x;
    int ebase = blockIdx.x * 128;
    int colbase = blockIdx.y * 128;

    if (tid < 128) sbias[tid] = b2[colbase + tid];

    // A tile: 128 rows x 128 k (uint4 = 8 halves). Zero-fill past E.
#pragma unroll
    for (int it = 0; it < 8; it++) {
        int idx = it * 256 + tid;        // 0..2047
        int r = idx >> 4, c = idx & 15;
        uint4 v = make_uint4(0, 0, 0, 0);
        if (ebase + r < E)
            v = *(const uint4*)(g_hr_h + ((size_t)(ebase + r) << 7) + c * 8);
        *(uint4*)(As + r * WSTRIDE + c * 8) = v;
    }
    // B tile: 128 n-rows x 128 k
#pragma unroll
    for (int it = 0; it < 8; it++) {
        int idx = it * 256 + tid;
        int r = idx >> 4, c = idx & 15;
        uint4 v = *(const uint4*)(g_W2T + ((size_t)(colbase + r) << 7) + c * 8);
        *(uint4*)(Bs + r * WSTRIDE + c * 8) = v;
    }
    __syncthreads();

    int w = tid >> 5, lane = tid & 31;
    int wm = (w & 3) * 32;    // warp M offset (4 warps)
    int wn = (w >> 2) * 64;   // warp N offset (2 warps)

    float acc[2][8][4];
#pragma unroll
    for (int i = 0; i < 2; i++)
#pragma unroll
        for (int j = 0; j < 8; j++)
#pragma unroll
            for (int q = 0; q < 4; q++) acc[i][j][q] = 0.f;

    // per-thread ldmatrix base addresses (k=0)
    // A frag i: row = wm + i*16 + (lane&15), col = (lane>>4)*8
    uint32_t a_addr[2];
#pragma unroll
    for (int i = 0; i < 2; i++)
        a_addr[i] = sbase + AS_OFF +
                    (uint32_t)((wm + i * 16 + (lane & 15)) * WSTRIDE +
                               (lane >> 4) * 8) * 2;
    // B frag-pair jj (covers n-frags 2jj,2jj+1):
    // row = wn + jj*16 + ((lane>>4)&1)*8 + (lane&7), col = ((lane>>3)&1)*8
    uint32_t b_addr[4];
#pragma unroll
    for (int jj = 0; jj < 4; jj++)
        b_addr[jj] = sbase + BS_OFF +
                     (uint32_t)((wn + jj * 16 + ((lane >> 4) & 1) * 8 + (lane & 7)) *
                                    WSTRIDE +
                                ((lane >> 3) & 1) * 8) * 2;

#pragma unroll
    for (int s = 0; s < 8; s++) {
        uint32_t a[2][4], b[4][4];
#pragma unroll
        for (int i = 0; i < 2; i++) ldsm4(a[i], a_addr[i] + s * 32);
#pragma unroll
        for (int jj = 0; jj < 4; jj++) ldsm4(b[jj], b_addr[jj] + s * 32);
#pragma unroll
        for (int i = 0; i < 2; i++)
#pragma unroll
            for (int jj = 0; jj < 4; jj++) {
                mma16816(acc[i][2 * jj], a[i], &b[jj][0]);
                mma16816(acc[i][2 * jj + 1], a[i], &b[jj][2]);
            }
    }
    __syncthreads();   // done with A/B tiles; reuse As as fp16 C staging

    // write accums (+bias, fp16) into staging smem
    __half* Cs = As;
    int g = lane >> 2, tg = lane & 3;
#pragma unroll
    for (int i = 0; i < 2; i++) {
#pragma unroll
        for (int j = 0; j < 8; j++) {
            int col = wn + j * 8 + tg * 2;
            float b0 = sbias[col], b1 = sbias[col + 1];
            int r0 = wm + i * 16 + g;
            __half2 h0 = __floats2half2_rn(acc[i][j][0] + b0, acc[i][j][1] + b1);
            __half2 h1 = __floats2half2_rn(acc[i][j][2] + b0, acc[i][j][3] + b1);
            *(__half2*)(Cs + r0 * WSTRIDE + col) = h0;
            *(__half2*)(Cs + (r0 + 8) * WSTRIDE + col) = h1;
        }
    }
    __syncthreads();

    // coalesced store
#pragma unroll
    for (int it = 0; it < 8; it++) {
        int idx = it * 256 + tid;
        int r = idx >> 4, c = idx & 15;
        if (ebase + r < E) {
            uint4 v = *(const uint4*)(Cs + r * WSTRIDE + c * 8);
            *(uint4*)(g_Wedge_h + (size_t)(ebase + r) * 4096 + colbase + c * 8) = v;
        }
    }
}

// msg[e] = h[src[e]] @ Wedge_h[e] (fp16 weights, fp32 accumulate);
// atomically scattered to g_agg[dst[e]]. 32 edges/block, 8 threads/edge x 8 cols.
__global__ void __launch_bounds__(256) msg_scatter_kernel(
    const int* __restrict__ src, const int* __restrict__ dst, int E) {
    __shared__ float outs[32][68];
    __shared__ int sdst[32];
    int ty = threadIdx.x >> 3;
    int tx = threadIdx.x & 7;
    int e = blockIdx.x * 32 + ty;
    if (e < E) {
        int s = src[e];
        *(float4*)&outs[ty][tx * 8] = *(const float4*)&g_h[(size_t)s * 64 + tx * 8];
        *(float4*)&outs[ty][tx * 8 + 4] =
            *(const float4*)&g_h[(size_t)s * 64 + tx * 8 + 4];
        if (tx == 0) sdst[ty] = dst[e];
    }
    __syncthreads();
    if (e >= E) return;
    float acc[8];
#pragma unroll
    for (int j = 0; j < 8; j++) acc[j] = 0.f;
    const __half* Wrow = g_Wedge_h + (size_t)e * 4096 + tx * 8;
#pragma unroll 4
    for (int d = 0; d < 64; d++) {
        float a = outs[ty][d];
        uint4 raw = *(const uint4*)(Wrow + d * 64);
        float2 f0 = __half22float2(*(__half2*)&raw.x);
        float2 f1 = __half22float2(*(__half2*)&raw.y);
        float2 f2 = __half22float2(*(__half2*)&raw.z);
        float2 f3 = __half22float2(*(__half2*)&raw.w);
        acc[0] += a * f0.x; acc[1] += a * f0.y;
        acc[2] += a * f1.x; acc[3] += a * f1.y;
        acc[4] += a * f2.x; acc[5] += a * f2.y;
        acc[6] += a * f3.x; acc[7] += a * f3.y;
    }
    int dn = sdst[ty];
    float* ap = g_agg + (size_t)dn * 64 + tx * 8;
#pragma unroll
    for (int j = 0; j < 8; j++) atomicAdd(ap + j, acc[j]);
}

// GRU update, 32 nodes per block; register-blocked 8 nodes/thread.
#define GRU_NODES 32
#define GRU_SMEM_FLOATS (2 * 192 * 65 + 2 * GRU_NODES * 64)
__global__ void __launch_bounds__(256) gru_kernel(
    const float* __restrict__ conv_bias,
    const float* __restrict__ W_ih, const float* __restrict__ b_ih,
    const float* __restrict__ W_hh, const float* __restrict__ b_hh, int N) {
    extern __shared__ float sm[];
    float* wih = sm;
    float* whh = sm + 192 * 65;
    float* ms  = whh + 192 * 65;
    float* hs  = ms + GRU_NODES * 64;
    int tid = threadIdx.x;
    for (int i = tid; i < 192 * 64; i += 256) {
        int j = i >> 6, k = i & 63;
        wih[j * 65 + k] = W_ih[i];
        whh[j * 65 + k] = W_hh[i];
    }
    int nb = blockIdx.x * GRU_NODES;
    for (int i = tid; i < GRU_NODES * 64; i += 256) {
        int nl = i >> 6, f = i & 63;
        int n = nb + nl;
        if (n < N) {
            ms[nl * 64 + f] =
                fmaxf(g_agg[(size_t)n * 64 + f] * g_invcnt[n] + conv_bias[f], 0.f);
            hs[nl * 64 + f] = g_h[(size_t)n * 64 + f];
        }
    }
    __syncthreads();
    int lane = tid & 63;
    int grp = tid >> 6;
    float aR[8], aZ[8], aN[8], bR[8], bZ[8], bN[8];
    {
        float bir = b_ih[lane], biz = b_ih[64 + lane], bin = b_ih[128 + lane];
        float bhr = b_hh[lane], bhz = b_hh[64 + lane], bhn = b_hh[128 + lane];
#pragma unroll
        for (int j = 0; j < 8; j++) {
            aR[j] = bir; aZ[j] = biz; aN[j] = bin;
            bR[j] = bhr; bZ[j] = bhz; bN[j] = bhn;
        }
    }
    const float* msg = ms + grp * 8 * 64;
    const float* hsg = hs + grp * 8 * 64;
#pragma unroll 2
    for (int k = 0; k < 64; k++) {
        float w0 = wih[lane * 65 + k];
        float w1 = wih[(64 + lane) * 65 + k];
        float w2 = wih[(128 + lane) * 65 + k];
        float v0 = whh[lane * 65 + k];
        float v1 = whh[(64 + lane) * 65 + k];
        float v2 = whh[(128 + lane) * 65 + k];
#pragma unroll
        for (int j = 0; j < 8; j++) {
            float mk = msg[j * 64 + k];
            float hk = hsg[j * 64 + k];
            aR[j] += mk * w0; aZ[j] += mk * w1; aN[j] += mk * w2;
            bR[j] += hk * v0; bZ[j] += hk * v1; bN[j] += hk * v2;
        }
    }
#pragma unroll
    for (int j = 0; j < 8; j++) {
        int n = nb + grp * 8 + j;
        if (n >= N) continue;
        float r = 1.f / (1.f + __expf(-(aR[j] + bR[j])));
        float z = 1.f / (1.f + __expf(-(aZ[j] + bZ[j])));
        float ng = tanhf(aN[j] + r * bN[j]);
        g_h[(size_t)n * 64 + lane] = (1.f - z) * ng + z * hsg[j * 64 + lane];
    }
}

// final: feat=[0.5*(h[a]+h[b]) (64) | edge_attr3 (8)]; y = relu(feat@W_l1+b_l1)@W_l2+b_l2
#define FIN_PER_BLOCK 32
__global__ void __launch_bounds__(128) final_mlp_kernel(
    const float* __restrict__ ea3, const int* __restrict__ idx_a,
    const int* __restrict__ idx_b, const float* __restrict__ W_l1,
    const float* __restrict__ b_l1, const float* __restrict__ W_l2,
    const float* __restrict__ b_l2, float* __restrict__ out, int E3) {
    __shared__ float wl1[72 * 128];
    __shared__ float wl2[128];
    __shared__ float feat[72];
    __shared__ float red[4];
    int tid = threadIdx.x;
    for (int i = tid; i < 72 * 128; i += 128) wl1[i] = W_l1[i];
    wl2[tid] = W_l2[tid];
    float bl1 = b_l1[tid];
    int base = blockIdx.x * FIN_PER_BLOCK;
    for (int t = 0; t < FIN_PER_BLOCK; t++) {
        int e = base + t;
        if (e >= E3) break;
        __syncthreads();
        if (tid < 64) {
            int a = idx_a[e], b = idx_b[e];
            feat[tid] = 0.5f * (g_h[(size_t)a * 64 + tid] + g_h[(size_t)b * 64 + tid]);
        } else if (tid < 72) {
            feat[tid] = ea3[(size_t)e * 8 + (tid - 64)];
        }
        __syncthreads();
        float acc = bl1;
#pragma unroll
        for (int i = 0; i < 72; i++) acc += feat[i] * wl1[i * 128 + tid];
        acc = fmaxf(acc, 0.f) * wl2[tid];
#pragma unroll
        for (int o = 16; o > 0; o >>= 1) acc += __shfl_down_sync(0xffffffffu, acc, o);
        if ((tid & 31) == 0) red[tid >> 5] = acc;
        __syncthreads();
        if (tid == 0) out[e] = red[0] + red[1] + red[2] + red[3] + b_l2[0];
    }
}

// ---------------- launch ------------------------------------------------------
extern "C" void kernel_launch(void* const* d_in, const int* in_sizes, int n_in,
                              void* d_out, int out_size) {
    const float* x          = (const float*)d_in[0];
    const float* edge_attr  = (const float*)d_in[1];
    const float* edge_attr3 = (const float*)d_in[2];
    const int*   edge_index  = (const int*)d_in[3];
    const int*   edge_index3 = (const int*)d_in[4];
    const float* W_node = (const float*)d_in[5];
    const float* b_node = (const float*)d_in[6];
    const float* W_ea   = (const float*)d_in[7];
    const float* b_ea   = (const float*)d_in[8];
    const float* W_e1   = (const float*)d_in[9];
    const float* b_e1   = (const float*)d_in[10];
    const float* W_e2   = (const float*)d_in[11];
    const float* b_e2   = (const float*)d_in[12];
    const float* conv_bias = (const float*)d_in[13];
    const float* W_ih = (const float*)d_in[14];
    const float* b_ih = (const float*)d_in[15];
    const float* W_hh = (const float*)d_in[16];
    const float* b_hh = (const float*)d_in[17];
    const float* W_l1 = (const float*)d_in[18];
    const float* b_l1 = (const float*)d_in[19];
    const float* W_l2 = (const float*)d_in[20];
    const float* b_l2 = (const float*)d_in[21];

    int N  = in_sizes[0] / 8;
    int E  = in_sizes[1] / 19;
    int E3 = in_sizes[2] / 8;
    const int* src  = edge_index;
    const int* dst  = edge_index + E;
    const int* e3a  = edge_index3;
    const int* e3b  = edge_index3 + E3;
    float* out = (float*)d_out;

    cudaFuncSetAttribute(gru_kernel, cudaFuncAttributeMaxDynamicSharedMemorySize,
                         GRU_SMEM_FLOATS * (int)sizeof(float));
    cudaFuncSetAttribute(wedge_mma_kernel,
                         cudaFuncAttributeMaxDynamicSharedMemorySize, WM_SMEM_SIZE);

    // 1. node MLP
    node_mlp_kernel<<<(N * DIM + 255) / 256, 256>>>(x, W_node, b_node, N);
    // 2. edge MLP -> hr (fp16)
    edge_mlp_kernel<<<E, 128>>>(edge_attr, W_ea, b_ea, W_e1, b_e1, E);
    // 3. W_e2 -> fp16 transposed
    w2_transpose_kernel<<<(4096 * 128 + 255) / 256, 256>>>(W_e2);
    // 4. big GEMM on tensor cores (HMMA) -> Wedge (fp16)
    {
        dim3 grid((E + 127) / 128, 32);
        wedge_mma_kernel<<<grid, 256, WM_SMEM_SIZE>>>(b_e2, E);
    }
    // degree counts
    zero_cnt_kernel<<<(N + 255) / 256, 256>>>(N);
    count_kernel<<<(E + 255) / 256, 256>>>(dst, E);
    invcnt_kernel<<<(N + 255) / 256, 256>>>(N);
    // three conv + GRU iterations
    for (int it = 0; it < 3; it++) {
        zero_agg_kernel<<<(N * DIM + 255) / 256, 256>>>(N * DIM);
        msg_scatter_kernel<<<(E + 31) / 32, 256>>>(src, dst, E);
        gru_kernel<<<(N + GRU_NODES - 1) / GRU_NODES, 256,
                     GRU_SMEM_FLOATS * (int)sizeof(float)>>>(
            conv_bias, W_ih, b_ih, W_hh, b_hh, N);
    }
    // final pair MLP
    final_mlp_kernel<<<(E3 + FIN_PER_BLOCK - 1) / FIN_PER_BLOCK, 128>>>(
        edge_attr3, e3a, e3b, W_l1, b_l1, W_l2, b_l2, out, E3);
}

// round 6
// speedup vs baseline: 4.4214x; 1.2791x over previous
#include <cuda_runtime.h>
#include <cuda_fp16.h>
#include <cstdint>
#include <cstddef>

#define NN   25000
#define EE   50000
#define EE3  40000
#define DIM  64

// Wedge stored as e4m3 scaled by 32 (decoded value = stored/32)
#define WSCALE     32.0f
#define WSCALE_INV 0.03125f

// ---------------- scratch (device globals; no allocation at launch time) ----
__device__ float   g_h[NN * DIM];                      // node features / GRU state
__device__ float   g_agg[NN * DIM];                    // scatter-sum accumulator
__device__ __half  g_hr_h[EE * 128];                   // edge hidden (fp16)
__device__ __half  g_W2T[4096 * 128];                  // W_e2 transposed fp16 [col][k]
__device__ uint8_t g_Wedge8[(size_t)EE * DIM * DIM];   // 205 MB per-edge weights (e4m3*32)
__device__ float   g_cnt[NN];
__device__ float   g_invcnt[NN];

// ---------------- helpers -----------------------------------------------------
__device__ __forceinline__ uint32_t smem_to_u32(const void* p) {
    uint32_t a;
    asm("{ .reg .u64 t; cvta.to.shared.u64 t, %1; cvt.u32.u64 %0, t; }"
        : "=r"(a) : "l"(p));
    return a;
}
__device__ __forceinline__ void ldsm4(uint32_t* r, uint32_t addr) {
    asm volatile("ldmatrix.sync.aligned.m8n8.x4.shared.b16 {%0,%1,%2,%3}, [%4];"
                 : "=r"(r[0]), "=r"(r[1]), "=r"(r[2]), "=r"(r[3]) : "r"(addr));
}
__device__ __forceinline__ void mma16816(float* d, const uint32_t* a,
                                         const uint32_t* b) {
    asm volatile(
        "mma.sync.aligned.m16n8k16.row.col.f32.f16.f16.f32 "
        "{%0,%1,%2,%3}, {%4,%5,%6,%7}, {%8,%9}, {%0,%1,%2,%3};"
        : "+f"(d[0]), "+f"(d[1]), "+f"(d[2]), "+f"(d[3])
        : "r"(a[0]), "r"(a[1]), "r"(a[2]), "r"(a[3]), "r"(b[0]), "r"(b[1]));
}
// pack 2 floats -> e4m3x2 (lo -> low byte, hi -> high byte)
__device__ __forceinline__ uint16_t f32x2_to_e4m3(float lo, float hi) {
    uint16_t r;
    asm("cvt.rn.satfinite.e4m3x2.f32 %0, %1, %2;" : "=h"(r) : "f"(hi), "f"(lo));
    return r;
}
// unpack e4m3x2 -> half2 (low byte -> low half)
__device__ __forceinline__ uint32_t e4m3x2_to_f16x2(uint16_t v) {
    uint32_t r;
    asm("cvt.rn.f16x2.e4m3x2 %0, %1;" : "=r"(r) : "h"(v));
    return r;
}
// f32x2 fma (used by GRU)
__device__ __forceinline__ unsigned long long fma2(unsigned long long a,
                                                   unsigned long long b,
                                                   unsigned long long c) {
    unsigned long long d;
    asm("fma.rn.f32x2 %0, %1, %2, %3;" : "=l"(d) : "l"(a), "l"(b), "l"(c));
    return d;
}
__device__ __forceinline__ float2 unpack2(unsigned long long v) {
    float2 r;
    asm("mov.b64 {%0, %1}, %2;" : "=f"(r.x), "=f"(r.y) : "l"(v));
    return r;
}

// ---------------- small kernels ----------------------------------------------
__global__ void zero_agg_kernel(int n) {
    int i = blockIdx.x * 256 + threadIdx.x;
    if (i < n) g_agg[i] = 0.f;
}
__global__ void zero_cnt_kernel(int n) {
    int i = blockIdx.x * 256 + threadIdx.x;
    if (i < n) g_cnt[i] = 0.f;
}
__global__ void count_kernel(const int* __restrict__ dst, int E) {
    int e = blockIdx.x * 256 + threadIdx.x;
    if (e < E) atomicAdd(&g_cnt[dst[e]], 1.f);
}
__global__ void invcnt_kernel(int N) {
    int i = blockIdx.x * 256 + threadIdx.x;
    if (i < N) g_invcnt[i] = 1.f / fmaxf(g_cnt[i], 1.f);
}

// out = relu(x @ W_node + b_node)   [N,8]x[8,64]
__global__ void node_mlp_kernel(const float* __restrict__ x,
                                const float* __restrict__ Wn,
                                const float* __restrict__ bn, int N) {
    int i = blockIdx.x * 256 + threadIdx.x;
    if (i >= N * DIM) return;
    int n = i >> 6, f = i & 63;
    float acc = bn[f];
#pragma unroll
    for (int k = 0; k < 8; k++) acc += x[n * 8 + k] * Wn[k * DIM + f];
    g_h[i] = fmaxf(acc, 0.f);
}

// W_e2 [128,4096] fp32 -> g_W2T [4096][128] fp16
__global__ void w2_transpose_kernel(const float* __restrict__ W2) {
    int i = blockIdx.x * 256 + threadIdx.x;
    if (i >= 4096 * 128) return;
    int n = i & 4095, k = i >> 12;
    g_W2T[(size_t)n * 128 + k] = __float2half(W2[(size_t)k * 4096 + n]);
}

// per-edge: ea = relu(edge_attr@W_ea+b_ea) [19->12]; hr = relu(ea@W_e1+b_e1) [12->128] fp16
__global__ void __launch_bounds__(128) edge_mlp_kernel(
    const float* __restrict__ ea_in, const float* __restrict__ W_ea,
    const float* __restrict__ b_ea, const float* __restrict__ W_e1,
    const float* __restrict__ b_e1, int E) {
    __shared__ float row[19];
    __shared__ float eah[12];
    int e = blockIdx.x;
    int tid = threadIdx.x;
    if (tid < 19) row[tid] = ea_in[(size_t)e * 19 + tid];
    __syncthreads();
    if (tid < 12) {
        float a = b_ea[tid];
#pragma unroll
        for (int i = 0; i < 19; i++) a += row[i] * W_ea[i * 12 + tid];
        eah[tid] = fmaxf(a, 0.f);
    }
    __syncthreads();
    float a = b_e1[tid];
#pragma unroll
    for (int k = 0; k < 12; k++) a += eah[k] * W_e1[k * 128 + tid];
    g_hr_h[(size_t)e * 128 + tid] = __float2half(fmaxf(a, 0.f));
}

// ============ HMMA Wedge GEMM (fp16 in, fp32 acc, e4m3*32 out) ================
#define WSTRIDE 136
#define AS_OFF  0
#define BS_OFF  (128 * WSTRIDE * 2)
#define BIAS_OFF (2 * 128 * WSTRIDE * 2)
#define WM_SMEM_SIZE (BIAS_OFF + 128 * 4)
#define CBSTR 144   // byte stride of fp8 staging rows (16-aligned)

__global__ void __launch_bounds__(256) wedge_mma_kernel(
    const float* __restrict__ b2, int E) {
    extern __shared__ char smem[];
    __half* As = (__half*)(smem + AS_OFF);
    __half* Bs = (__half*)(smem + BS_OFF);
    float* sbias = (float*)(smem + BIAS_OFF);
    uint32_t sbase = smem_to_u32(smem);
    int tid = threadIdx.x;
    int ebase = blockIdx.x * 128;
    int colbase = blockIdx.y * 128;

    if (tid < 128) sbias[tid] = b2[colbase + tid];

    // A tile: 128 rows x 128 k. Zero-fill past E.
#pragma unroll
    for (int it = 0; it < 8; it++) {
        int idx = it * 256 + tid;
        int r = idx >> 4, c = idx & 15;
        uint4 v = make_uint4(0, 0, 0, 0);
        if (ebase + r < E)
            v = *(const uint4*)(g_hr_h + ((size_t)(ebase + r) << 7) + c * 8);
        *(uint4*)(As + r * WSTRIDE + c * 8) = v;
    }
    // B tile: 128 n-rows x 128 k
#pragma unroll
    for (int it = 0; it < 8; it++) {
        int idx = it * 256 + tid;
        int r = idx >> 4, c = idx & 15;
        uint4 v = *(const uint4*)(g_W2T + ((size_t)(colbase + r) << 7) + c * 8);
        *(uint4*)(Bs + r * WSTRIDE + c * 8) = v;
    }
    __syncthreads();

    int w = tid >> 5, lane = tid & 31;
    int wm = (w & 3) * 32;
    int wn = (w >> 2) * 64;

    float acc[2][8][4];
#pragma unroll
    for (int i = 0; i < 2; i++)
#pragma unroll
        for (int j = 0; j < 8; j++)
#pragma unroll
            for (int q = 0; q < 4; q++) acc[i][j][q] = 0.f;

    uint32_t a_addr[2];
#pragma unroll
    for (int i = 0; i < 2; i++)
        a_addr[i] = sbase + AS_OFF +
                    (uint32_t)((wm + i * 16 + (lane & 15)) * WSTRIDE +
                               (lane >> 4) * 8) * 2;
    uint32_t b_addr[4];
#pragma unroll
    for (int jj = 0; jj < 4; jj++)
        b_addr[jj] = sbase + BS_OFF +
                     (uint32_t)((wn + jj * 16 + ((lane >> 4) & 1) * 8 + (lane & 7)) *
                                    WSTRIDE +
                                ((lane >> 3) & 1) * 8) * 2;

#pragma unroll
    for (int s = 0; s < 8; s++) {
        uint32_t a[2][4], b[4][4];
#pragma unroll
        for (int i = 0; i < 2; i++) ldsm4(a[i], a_addr[i] + s * 32);
#pragma unroll
        for (int jj = 0; jj < 4; jj++) ldsm4(b[jj], b_addr[jj] + s * 32);
#pragma unroll
        for (int i = 0; i < 2; i++)
#pragma unroll
            for (int jj = 0; jj < 4; jj++) {
                mma16816(acc[i][2 * jj], a[i], &b[jj][0]);
                mma16816(acc[i][2 * jj + 1], a[i], &b[jj][2]);
            }
    }
    __syncthreads();   // reuse As region as fp8 staging

    uint8_t* Cs = (uint8_t*)smem;
    int g = lane >> 2, tg = lane & 3;
#pragma unroll
    for (int i = 0; i < 2; i++) {
#pragma unroll
        for (int j = 0; j < 8; j++) {
            int col = wn + j * 8 + tg * 2;
            float b0 = sbias[col], b1 = sbias[col + 1];
            int r0 = wm + i * 16 + g;
            uint16_t p0 = f32x2_to_e4m3((acc[i][j][0] + b0) * WSCALE,
                                        (acc[i][j][1] + b1) * WSCALE);
            uint16_t p1 = f32x2_to_e4m3((acc[i][j][2] + b0) * WSCALE,
                                        (acc[i][j][3] + b1) * WSCALE);
            *(uint16_t*)(Cs + r0 * CBSTR + col) = p0;
            *(uint16_t*)(Cs + (r0 + 8) * CBSTR + col) = p1;
        }
    }
    __syncthreads();

    // coalesced 16B stores: 128 rows x 128 bytes
#pragma unroll
    for (int it = 0; it < 4; it++) {
        int idx = it * 256 + tid;          // 0..1023
        int r = idx >> 3, c = idx & 7;
        if (ebase + r < E) {
            uint4 v = *(const uint4*)(Cs + r * CBSTR + c * 16);
            *(uint4*)(g_Wedge8 + (size_t)(ebase + r) * 4096 + colbase + c * 16) = v;
        }
    }
}

// msg[e] = h[src[e]] @ Wedge8[e] (e4m3*32 weights, fp32 accumulate, /32 at end);
// 64 edges/block, 4 threads/edge x 16 cols (LDG.128 of 16 fp8 per d).
__global__ void __launch_bounds__(256) msg_scatter_kernel(
    const int* __restrict__ src, const int* __restrict__ dst, int E) {
    __shared__ float outs[64][68];
    __shared__ int sdst[64];
    int ty = threadIdx.x >> 2;   // edge slot 0..63
    int tx = threadIdx.x & 3;    // col group (16 cols)
    int e = blockIdx.x * 64 + ty;
    if (e < E) {
        int s = src[e];
#pragma unroll
        for (int q = 0; q < 4; q++)
            *(float4*)&outs[ty][tx * 16 + q * 4] =
                *(const float4*)&g_h[(size_t)s * 64 + tx * 16 + q * 4];
        if (tx == 0) sdst[ty] = dst[e];
    }
    __syncthreads();
    if (e >= E) return;
    float acc[16];
#pragma unroll
    for (int j = 0; j < 16; j++) acc[j] = 0.f;
    const uint8_t* Wrow = g_Wedge8 + (size_t)e * 4096 + tx * 16;
#pragma unroll 4
    for (int d = 0; d < 64; d++) {
        float a = outs[ty][d];
        uint4 raw = *(const uint4*)(Wrow + d * 64);
        uint32_t ws[4] = {raw.x, raw.y, raw.z, raw.w};
#pragma unroll
        for (int q = 0; q < 4; q++) {
            uint32_t h2lo = e4m3x2_to_f16x2((uint16_t)ws[q]);
            uint32_t h2hi = e4m3x2_to_f16x2((uint16_t)(ws[q] >> 16));
            float2 f0 = __half22float2(*(__half2*)&h2lo);
            float2 f1 = __half22float2(*(__half2*)&h2hi);
            acc[4 * q + 0] += a * f0.x;
            acc[4 * q + 1] += a * f0.y;
            acc[4 * q + 2] += a * f1.x;
            acc[4 * q + 3] += a * f1.y;
        }
    }
    int dn = sdst[ty];
    float* ap = g_agg + (size_t)dn * 64 + tx * 16;
#pragma unroll
    for (int j = 0; j < 16; j++) atomicAdd(ap + j, acc[j] * WSCALE_INV);
}

// GRU update: 16 nodes/block, f32x2 over k-pairs (paired LDS.64 + fma2).
#define GRU_NODES 16
#define GRU_SMEM_FLOATS (2 * 192 * 66 + 2 * GRU_NODES * 64)
__global__ void __launch_bounds__(256) gru_kernel(
    const float* __restrict__ conv_bias,
    const float* __restrict__ W_ih, const float* __restrict__ b_ih,
    const float* __restrict__ W_hh, const float* __restrict__ b_hh, int N) {
    extern __shared__ float sm[];
    float* wih = sm;                     // [192][66] padded
    float* whh = sm + 192 * 66;
    float* ms  = whh + 192 * 66;         // [16][64]
    float* hs  = ms + GRU_NODES * 64;
    int tid = threadIdx.x;
    for (int i = tid; i < 192 * 64; i += 256) {
        int j = i >> 6, k = i & 63;
        wih[j * 66 + k] = W_ih[i];
        whh[j * 66 + k] = W_hh[i];
    }
    int nb = blockIdx.x * GRU_NODES;
    for (int i = tid; i < GRU_NODES * 64; i += 256) {
        int nl = i >> 6, f = i & 63;
        int n = nb + nl;
        if (n < N) {
            ms[nl * 64 + f] =
                fmaxf(g_agg[(size_t)n * 64 + f] * g_invcnt[n] + conv_bias[f], 0.f);
            hs[nl * 64 + f] = g_h[(size_t)n * 64 + f];
        }
    }
    __syncthreads();
    int lane = tid & 63;   // feature f
    int grp = tid >> 6;    // 0..3 -> nodes grp*4 .. grp*4+3
    unsigned long long aR[4], aZ[4], aN[4], bR[4], bZ[4], bN[4];
#pragma unroll
    for (int j = 0; j < 4; j++) {
        aR[j] = aZ[j] = aN[j] = 0ull;
        bR[j] = bZ[j] = bN[j] = 0ull;
    }
    const float* msg = ms + grp * 4 * 64;
    const float* hsg = hs + grp * 4 * 64;
#pragma unroll 4
    for (int k = 0; k < 64; k += 2) {
        unsigned long long w0 = *(const unsigned long long*)&wih[lane * 66 + k];
        unsigned long long w1 = *(const unsigned long long*)&wih[(64 + lane) * 66 + k];
        unsigned long long w2 = *(const unsigned long long*)&wih[(128 + lane) * 66 + k];
        unsigned long long v0 = *(const unsigned long long*)&whh[lane * 66 + k];
        unsigned long long v1 = *(const unsigned long long*)&whh[(64 + lane) * 66 + k];
        unsigned long long v2 = *(const unsigned long long*)&whh[(128 + lane) * 66 + k];
#pragma unroll
        for (int j = 0; j < 4; j++) {
            unsigned long long mk = *(const unsigned long long*)&msg[j * 64 + k];
            unsigned long long hk = *(const unsigned long long*)&hsg[j * 64 + k];
            aR[j] = fma2(mk, w0, aR[j]);
            aZ[j] = fma2(mk, w1, aZ[j]);
            aN[j] = fma2(mk, w2, aN[j]);
            bR[j] = fma2(hk, v0, bR[j]);
            bZ[j] = fma2(hk, v1, bZ[j]);
            bN[j] = fma2(hk, v2, bN[j]);
        }
    }
    float bir = b_ih[lane], biz = b_ih[64 + lane], bin = b_ih[128 + lane];
    float bhr = b_hh[lane], bhz = b_hh[64 + lane], bhn = b_hh[128 + lane];
#pragma unroll
    for (int j = 0; j < 4; j++) {
        int n = nb + grp * 4 + j;
        if (n >= N) continue;
        float2 pr = unpack2(aR[j]);
        float2 pz = unpack2(aZ[j]);
        float2 pn = unpack2(aN[j]);
        float2 qr = unpack2(bR[j]);
        float2 qz = unpack2(bZ[j]);
        float2 qn = unpack2(bN[j]);
        float ir = pr.x + pr.y + bir, iz = pz.x + pz.y + biz, inn = pn.x + pn.y + bin;
        float hrr = qr.x + qr.y + bhr, hz = qz.x + qz.y + bhz, hn = qn.x + qn.y + bhn;
        float r = 1.f / (1.f + __expf(-(ir + hrr)));
        float z = 1.f / (1.f + __expf(-(iz + hz)));
        float ng = tanhf(inn + r * hn);
        g_h[(size_t)n * 64 + lane] = (1.f - z) * ng + z * hsg[j * 64 + lane];
    }
}

// final MLP: warp-per-edge, weights staged once, no block syncs in edge loop.
#define FIN_EDGES 64
__global__ void __launch_bounds__(128) final_mlp_kernel(
    const float* __restrict__ ea3, const int* __restrict__ idx_a,
    const int* __restrict__ idx_b, const float* __restrict__ W_l1,
    const float* __restrict__ b_l1, const float* __restrict__ W_l2,
    const float* __restrict__ b_l2, float* __restrict__ out, int E3) {
    __shared__ float wl1[72 * 128];
    __shared__ float swl2[128];
    __shared__ float sbl1[128];
    __shared__ float feat[4][72];
    int tid = threadIdx.x;
    for (int i = tid; i < 72 * 128; i += 128) wl1[i] = W_l1[i];
    swl2[tid] = W_l2[tid];
    sbl1[tid] = b_l1[tid];
    __syncthreads();
    int w = tid >> 5, lane = tid & 31;
    float bl2v = b_l2[0];
    int base = blockIdx.x * FIN_EDGES;
    for (int t = w; t < FIN_EDGES; t += 4) {
        int e = base + t;
        if (e >= E3) break;
        int a = idx_a[e], b = idx_b[e];
        feat[w][lane] =
            0.5f * (g_h[(size_t)a * 64 + lane] + g_h[(size_t)b * 64 + lane]);
        feat[w][32 + lane] = 0.5f * (g_h[(size_t)a * 64 + 32 + lane] +
                                     g_h[(size_t)b * 64 + 32 + lane]);
        if (lane < 8) feat[w][64 + lane] = ea3[(size_t)e * 8 + lane];
        __syncwarp();
        float a0 = sbl1[lane], a1 = sbl1[lane + 32],
              a2 = sbl1[lane + 64], a3 = sbl1[lane + 96];
#pragma unroll 8
        for (int i = 0; i < 72; i++) {
            float f = feat[w][i];
            a0 += f * wl1[i * 128 + lane];
            a1 += f * wl1[i * 128 + lane + 32];
            a2 += f * wl1[i * 128 + lane + 64];
            a3 += f * wl1[i * 128 + lane + 96];
        }
        float s = fmaxf(a0, 0.f) * swl2[lane] + fmaxf(a1, 0.f) * swl2[lane + 32] +
                  fmaxf(a2, 0.f) * swl2[lane + 64] + fmaxf(a3, 0.f) * swl2[lane + 96];
#pragma unroll
        for (int o = 16; o > 0; o >>= 1) s += __shfl_down_sync(0xffffffffu, s, o);
        if (lane == 0) out[e] = s + bl2v;
        __syncwarp();
    }
}

// ---------------- launch ------------------------------------------------------
extern "C" void kernel_launch(void* const* d_in, const int* in_sizes, int n_in,
                              void* d_out, int out_size) {
    const float* x          = (const float*)d_in[0];
    const float* edge_attr  = (const float*)d_in[1];
    const float* edge_attr3 = (const float*)d_in[2];
    const int*   edge_index  = (const int*)d_in[3];
    const int*   edge_index3 = (const int*)d_in[4];
    const float* W_node = (const float*)d_in[5];
    const float* b_node = (const float*)d_in[6];
    const float* W_ea   = (const float*)d_in[7];
    const float* b_ea   = (const float*)d_in[8];
    const float* W_e1   = (const float*)d_in[9];
    const float* b_e1   = (const float*)d_in[10];
    const float* W_e2   = (const float*)d_in[11];
    const float* b_e2   = (const float*)d_in[12];
    const float* conv_bias = (const float*)d_in[13];
    const float* W_ih = (const float*)d_in[14];
    const float* b_ih = (const float*)d_in[15];
    const float* W_hh = (const float*)d_in[16];
    const float* b_hh = (const float*)d_in[17];
    const float* W_l1 = (const float*)d_in[18];
    const float* b_l1 = (const float*)d_in[19];
    const float* W_l2 = (const float*)d_in[20];
    const float* b_l2 = (const float*)d_in[21];

    int N  = in_sizes[0] / 8;
    int E  = in_sizes[1] / 19;
    int E3 = in_sizes[2] / 8;
    const int* src  = edge_index;
    const int* dst  = edge_index + E;
    const int* e3a  = edge_index3;
    const int* e3b  = edge_index3 + E3;
    float* out = (float*)d_out;

    cudaFuncSetAttribute(gru_kernel, cudaFuncAttributeMaxDynamicSharedMemorySize,
                         GRU_SMEM_FLOATS * (int)sizeof(float));
    cudaFuncSetAttribute(wedge_mma_kernel,
                         cudaFuncAttributeMaxDynamicSharedMemorySize, WM_SMEM_SIZE);

    // 1. node MLP
    node_mlp_kernel<<<(N * DIM + 255) / 256, 256>>>(x, W_node, b_node, N);
    // 2. edge MLP -> hr (fp16)
    edge_mlp_kernel<<<E, 128>>>(edge_attr, W_ea, b_ea, W_e1, b_e1, E);
    // 3. W_e2 -> fp16 transposed
    w2_transpose_kernel<<<(4096 * 128 + 255) / 256, 256>>>(W_e2);
    // 4. big GEMM on tensor cores (HMMA) -> Wedge (e4m3*32)
    {
        dim3 grid((E + 127) / 128, 32);
        wedge_mma_kernel<<<grid, 256, WM_SMEM_SIZE>>>(b_e2, E);
    }
    // degree counts
    zero_cnt_kernel<<<(N + 255) / 256, 256>>>(N);
    count_kernel<<<(E + 255) / 256, 256>>>(dst, E);
    invcnt_kernel<<<(N + 255) / 256, 256>>>(N);
    // three conv + GRU iterations
    for (int it = 0; it < 3; it++) {
        zero_agg_kernel<<<(N * DIM + 255) / 256, 256>>>(N * DIM);
        msg_scatter_kernel<<<(E + 63) / 64, 256>>>(src, dst, E);
        gru_kernel<<<(N + GRU_NODES - 1) / GRU_NODES, 256,
                     GRU_SMEM_FLOATS * (int)sizeof(float)>>>(
            conv_bias, W_ih, b_ih, W_hh, b_hh, N);
    }
    // final pair MLP
    final_mlp_kernel<<<(E3 + FIN_EDGES - 1) / FIN_EDGES, 128>>>(
        edge_attr3, e3a, e3b, W_l1, b_l1, W_l2, b_l2, out, E3);
}